// round 7
// baseline (speedup 1.0000x reference)
#include <cuda_runtime.h>
#include <cuda_bf16.h>
#include <cstdint>

#define SEQ  8192
#define DIN  512
#define DOUT 64

#define NSPLIT 2
#define KEYS_PER_SPLIT (SEQ / NSPLIT)
#define BM 128
#define BN 64
#define NTILES (KEYS_PER_SPLIT / BN)   // 64

// ---------------- device scratch (no allocations allowed) ----------------
__device__ __align__(16) __nv_bfloat16 g_Qhi[SEQ*DOUT];
__device__ __align__(16) __nv_bfloat16 g_Qlo[SEQ*DOUT];
__device__ __align__(16) __nv_bfloat16 g_Khi[SEQ*DOUT];
__device__ __align__(16) __nv_bfloat16 g_Klo[SEQ*DOUT];
__device__ __align__(16) __nv_bfloat16 g_Vhi[SEQ*DOUT];
__device__ __align__(16) __nv_bfloat16 g_Vlo[SEQ*DOUT];
__device__ float g_Op[NSPLIT][SEQ*DOUT];
__device__ float g_m[NSPLIT][SEQ];
__device__ float g_l[NSPLIT][SEQ];

// ---------------- small helpers ----------------
__device__ __forceinline__ uint32_t smem_u32(const void* p) {
    return (uint32_t)__cvta_generic_to_shared((void*)p);
}
__device__ __forceinline__ float fexp2(float x) {
    float y;
    asm("ex2.approx.f32 %0, %1;" : "=f"(y) : "f"(x));
    return y;
}

// split (p0,p1) into packed bf16x2 hi + bf16x2 lo (residual)
__device__ __forceinline__ void split2(float p0, float p1, uint32_t& h, uint32_t& l) {
    uint32_t hh;
    asm("cvt.rn.bf16x2.f32 %0, %1, %2;" : "=r"(hh) : "f"(p1), "f"(p0));
    float f0 = __uint_as_float(hh << 16);
    float f1 = __uint_as_float(hh & 0xFFFF0000u);
    uint32_t ll;
    float r0 = p0 - f0, r1 = p1 - f1;
    asm("cvt.rn.bf16x2.f32 %0, %1, %2;" : "=r"(ll) : "f"(r1), "f"(r0));
    h = hh; l = ll;
}

__device__ __forceinline__ void mma16816(float c[4], const uint32_t a[4],
                                         uint32_t b0, uint32_t b1) {
    asm volatile("mma.sync.aligned.m16n8k16.row.col.f32.bf16.bf16.f32 "
        "{%0,%1,%2,%3}, {%4,%5,%6,%7}, {%8,%9}, {%0,%1,%2,%3};"
        : "+f"(c[0]), "+f"(c[1]), "+f"(c[2]), "+f"(c[3])
        : "r"(a[0]), "r"(a[1]), "r"(a[2]), "r"(a[3]), "r"(b0), "r"(b1));
}
__device__ __forceinline__ void ldsm4(uint32_t r[4], uint32_t addr) {
    asm volatile("ldmatrix.sync.aligned.m8n8.x4.shared.b16 {%0,%1,%2,%3}, [%4];"
        : "=r"(r[0]), "=r"(r[1]), "=r"(r[2]), "=r"(r[3]) : "r"(addr));
}
__device__ __forceinline__ void ldsm4t(uint32_t r[4], uint32_t addr) {
    asm volatile("ldmatrix.sync.aligned.m8n8.x4.trans.shared.b16 {%0,%1,%2,%3}, [%4];"
        : "=r"(r[0]), "=r"(r[1]), "=r"(r[2]), "=r"(r[3]) : "r"(addr));
}

// ============================================================
// Projection via HMMA split-bf16 (3 passes): out = x @ W.
// BM=64 rows/CTA -> grid (128, 3); 2 CTAs/SM resident; register
// prefetch pipelines kt+1's LDGs under kt's MMA phase.
// 8 warps: (wid&3) = m16 tile within 64 rows, (wid>>2) = n32 half.
// smem 32KB: XHI@0, XLO@8K, WHI@16K, WLO@24K; rows 128B,
// 16B chunk c of row r stored at (c ^ (r&7)).
// ============================================================
#define PJ_XHI 0
#define PJ_XLO 8192
#define PJ_WHI 16384
#define PJ_WLO 24576

__global__ __launch_bounds__(256, 2) void proj_kernel(
    const float* __restrict__ x,  const float* __restrict__ Wq,
    const float* __restrict__ Wk, const float* __restrict__ Wv)
{
    __shared__ __align__(16) char sm[32768];
    const uint32_t smb = smem_u32(sm);

    const int which = blockIdx.y;
    const float* W = (which == 0) ? Wq : ((which == 1) ? Wk : Wv);
    __nv_bfloat16* hiArr = (which == 0) ? g_Qhi : ((which == 1) ? g_Khi : g_Vhi);
    __nv_bfloat16* loArr = (which == 0) ? g_Qlo : ((which == 1) ? g_Klo : g_Vlo);
    // Q: 1/sqrt(64) * log2(e) so scores land in the log2 domain
    const float scale = (which == 0) ? 0.18033688011112042f : 1.0f;

    const int row0 = blockIdx.x * 64;
    const int tid  = threadIdx.x;
    const int lane = tid & 31;
    const int wid  = tid >> 5;
    const int wm   = (wid & 3) * 16;   // m16 tile
    const int nh   = (wid >> 2) * 32;  // n32 half

    // per-thread chunk coords (512 chunks per tile, 2/thread)
    const int i0 = tid, i1 = tid + 256;
    const int r0c = i0 >> 3, c0c = i0 & 7;
    const int r1c = i1 >> 3, c1c = i1 & 7;
    const int xoff0 = r0c * 128 + ((c0c ^ (r0c & 7)) << 4);
    const int xoff1 = r1c * 128 + ((c1c ^ (r1c & 7)) << 4);

    float C[4][4];
#pragma unroll
    for (int nt = 0; nt < 4; nt++)
#pragma unroll
        for (int c = 0; c < 4; c++) C[nt][c] = 0.0f;

    // prefetch kt=0
    float4 xa[2][2], wa[2][2];
    {
        const float* s0 = x + (row0 + r0c) * DIN + c0c * 8;
        const float* s1 = x + (row0 + r1c) * DIN + c1c * 8;
        xa[0][0] = *(const float4*)s0; xa[0][1] = *(const float4*)(s0 + 4);
        xa[1][0] = *(const float4*)s1; xa[1][1] = *(const float4*)(s1 + 4);
        const float* w0 = W + r0c * DOUT + c0c * 8;
        const float* w1 = W + r1c * DOUT + c1c * 8;
        wa[0][0] = *(const float4*)w0; wa[0][1] = *(const float4*)(w0 + 4);
        wa[1][0] = *(const float4*)w1; wa[1][1] = *(const float4*)(w1 + 4);
    }

    for (int kt = 0; kt < 8; kt++) {
        __syncthreads();   // prior MMA done reading smem
        // ---- convert + store prefetched x and W ----
#pragma unroll
        for (int j = 0; j < 2; j++) {
            uint32_t h0,l0,h1,l1,h2,l2,h3,l3;
            split2(xa[j][0].x, xa[j][0].y, h0, l0);
            split2(xa[j][0].z, xa[j][0].w, h1, l1);
            split2(xa[j][1].x, xa[j][1].y, h2, l2);
            split2(xa[j][1].z, xa[j][1].w, h3, l3);
            int off = (j == 0) ? xoff0 : xoff1;
            *(uint4*)(sm + PJ_XHI + off) = make_uint4(h0, h1, h2, h3);
            *(uint4*)(sm + PJ_XLO + off) = make_uint4(l0, l1, l2, l3);
            split2(wa[j][0].x, wa[j][0].y, h0, l0);
            split2(wa[j][0].z, wa[j][0].w, h1, l1);
            split2(wa[j][1].x, wa[j][1].y, h2, l2);
            split2(wa[j][1].z, wa[j][1].w, h3, l3);
            *(uint4*)(sm + PJ_WHI + off) = make_uint4(h0, h1, h2, h3);
            *(uint4*)(sm + PJ_WLO + off) = make_uint4(l0, l1, l2, l3);
        }
        // ---- prefetch kt+1 (in flight during MMA below) ----
        if (kt < 7) {
            const int k1 = (kt + 1) * 64;
            const float* s0 = x + (row0 + r0c) * DIN + k1 + c0c * 8;
            const float* s1 = x + (row0 + r1c) * DIN + k1 + c1c * 8;
            xa[0][0] = *(const float4*)s0; xa[0][1] = *(const float4*)(s0 + 4);
            xa[1][0] = *(const float4*)s1; xa[1][1] = *(const float4*)(s1 + 4);
            const float* w0 = W + (k1 + r0c) * DOUT + c0c * 8;
            const float* w1 = W + (k1 + r1c) * DOUT + c1c * 8;
            wa[0][0] = *(const float4*)w0; wa[0][1] = *(const float4*)(w0 + 4);
            wa[1][0] = *(const float4*)w1; wa[1][1] = *(const float4*)(w1 + 4);
        }
        __syncthreads();

        // ---- MMA for this kt ----
#pragma unroll
        for (int kc = 0; kc < 4; kc++) {
            int arow = wm + (lane & 7) + ((lane >> 3) & 1) * 8;
            int ach  = kc * 2 + (lane >> 4);
            uint32_t ad = smb + PJ_XHI + arow * 128 + ((ach ^ (arow & 7)) << 4);
            uint32_t ah[4], al[4];
            ldsm4(ah, ad);
            ldsm4(al, ad + 8192);
            uint32_t bh[2][4], bl[2][4];
            int krow = kc * 16 + (lane & 7) + ((lane >> 3) & 1) * 8;
#pragma unroll
            for (int p = 0; p < 2; p++) {
                int ch = (nh >> 3) + 2 * p + (lane >> 4);
                uint32_t bd = smb + PJ_WHI + krow * 128 + ((ch ^ (krow & 7)) << 4);
                ldsm4t(bh[p], bd);
                ldsm4t(bl[p], bd + 8192);
            }
#pragma unroll
            for (int nt = 0; nt < 4; nt++) {
                int p = nt >> 1, o = (nt & 1) * 2;
                mma16816(C[nt], ah, bh[p][o], bh[p][o+1]);
                mma16816(C[nt], ah, bl[p][o], bl[p][o+1]);
                mma16816(C[nt], al, bh[p][o], bh[p][o+1]);
            }
        }
    }

    // ---- epilogue: scale, split to bf16 hi/lo, store ----
    const int gid = lane >> 2, m4 = lane & 3;
#pragma unroll
    for (int nt = 0; nt < 4; nt++) {
        uint32_t h, l;
        const int row = row0 + wm + gid;
        const int col = nh + nt * 8 + m4 * 2;
        split2(C[nt][0] * scale, C[nt][1] * scale, h, l);
        *(uint32_t*)&hiArr[row * DOUT + col] = h;
        *(uint32_t*)&loArr[row * DOUT + col] = l;
        split2(C[nt][2] * scale, C[nt][3] * scale, h, l);
        *(uint32_t*)&hiArr[(row + 8) * DOUT + col] = h;
        *(uint32_t*)&loArr[(row + 8) * DOUT + col] = l;
    }
}

// ============================================================
// HMMA flash attention (split-bf16 3-pass), cp.async double-buffered.
// Scores arrive in log2 domain (log2e folded into Q) -> ex2 softmax.
// smem stage (32KB): KHI 0, KLO 8192, VHI 16384, VLO 24576; rows 128B,
// 16B-chunk xor-swizzle: chunk c of row r stored at (c ^ (r&7)).
// ============================================================
__device__ __forceinline__ void issue_tile_load(uint32_t smb, int stage, int kb, int tid) {
#pragma unroll
    for (int j = 0; j < 8; j++) {
        int i = tid + 256 * j;          // 0..2047
        int sel = i >> 9;               // 0 khi, 1 klo, 2 vhi, 3 vlo
        int r = (i >> 3) & 63;
        int c = i & 7;
        const __nv_bfloat16* base = (sel == 0) ? g_Khi : (sel == 1) ? g_Klo
                                  : (sel == 2) ? g_Vhi : g_Vlo;
        const __nv_bfloat16* src = base + (kb + r) * DOUT + c * 8;
        uint32_t dst = smb + stage * 32768 + sel * 8192 + r * 128 + ((c ^ (r & 7)) << 4);
        unsigned long long g = (unsigned long long)__cvta_generic_to_global((void*)src);
        asm volatile("cp.async.cg.shared.global [%0], [%1], 16;" :: "r"(dst), "l"(g) : "memory");
    }
}

__global__ __launch_bounds__(256, 1) void attn_kernel()
{
    extern __shared__ char sm[];
    const uint32_t smb = smem_u32(sm);
    const int tid  = threadIdx.x;
    const int lane = tid & 31;
    const int wid  = tid >> 5;
    const int gid  = lane >> 2;     // row group within fragment
    const int m4   = lane & 3;      // col pair within fragment
    const int row0 = blockIdx.x * BM;
    const int split = blockIdx.y;
    const int kb0  = split * KEYS_PER_SPLIT;
    const int q0   = row0 + wid * 16;

    // ---- persistent Q fragments (hi/lo), straight from gmem ----
    uint32_t qhi[4][4], qlo[4][4];
#pragma unroll
    for (int kc = 0; kc < 4; kc++) {
        const int base = (q0 + gid) * DOUT + kc * 16 + m4 * 2;
        qhi[kc][0] = *(const uint32_t*)&g_Qhi[base];
        qhi[kc][1] = *(const uint32_t*)&g_Qhi[base + 8*DOUT];
        qhi[kc][2] = *(const uint32_t*)&g_Qhi[base + 8];
        qhi[kc][3] = *(const uint32_t*)&g_Qhi[base + 8*DOUT + 8];
        qlo[kc][0] = *(const uint32_t*)&g_Qlo[base];
        qlo[kc][1] = *(const uint32_t*)&g_Qlo[base + 8*DOUT];
        qlo[kc][2] = *(const uint32_t*)&g_Qlo[base + 8];
        qlo[kc][3] = *(const uint32_t*)&g_Qlo[base + 8*DOUT + 8];
    }

    float O[8][4];
#pragma unroll
    for (int nt = 0; nt < 8; nt++)
#pragma unroll
        for (int c = 0; c < 4; c++) O[nt][c] = 0.0f;
    float mrow[2] = {-1e30f, -1e30f};
    float lrow[2] = {0.0f, 0.0f};

    issue_tile_load(smb, 0, kb0, tid);
    asm volatile("cp.async.commit_group;" ::: "memory");

    for (int t = 0; t < NTILES; t++) {
        if (t + 1 < NTILES) {
            issue_tile_load(smb, (t + 1) & 1, kb0 + (t + 1) * BN, tid);
            asm volatile("cp.async.commit_group;" ::: "memory");
            asm volatile("cp.async.wait_group 1;" ::: "memory");
        } else {
            asm volatile("cp.async.wait_group 0;" ::: "memory");
        }
        __syncthreads();

        const uint32_t bK = smb + (t & 1) * 32768;
        const uint32_t bV = bK + 16384;

        // ---- S = Q @ K^T (3 split passes), fp32 accum, log2 domain ----
        float S[8][4];
#pragma unroll
        for (int nt = 0; nt < 8; nt++)
#pragma unroll
            for (int c = 0; c < 4; c++) S[nt][c] = 0.0f;

#pragma unroll
        for (int kc = 0; kc < 4; kc++) {
            uint32_t bh[4][4], bl[4][4];
#pragma unroll
            for (int p = 0; p < 4; p++) {
                int key = p * 16 + (lane & 7) + ((lane >> 4) & 1) * 8;
                int ch  = kc * 2 + ((lane >> 3) & 1);
                uint32_t ad = bK + key * 128 + ((ch ^ (key & 7)) << 4);
                ldsm4(bh[p], ad);
                ldsm4(bl[p], ad + 8192);
            }
#pragma unroll
            for (int nt = 0; nt < 8; nt++) {
                int p = nt >> 1, o = (nt & 1) * 2;
                mma16816(S[nt], qhi[kc], bh[p][o], bh[p][o+1]);
                mma16816(S[nt], qhi[kc], bl[p][o], bl[p][o+1]);
                mma16816(S[nt], qlo[kc], bh[p][o], bh[p][o+1]);
            }
        }

        // ---- online softmax, base 2 (rows fully warp-local) ----
#pragma unroll
        for (int h = 0; h < 2; h++) {
            float mx = -1e30f;
#pragma unroll
            for (int nt = 0; nt < 8; nt++)
                mx = fmaxf(mx, fmaxf(S[nt][2*h], S[nt][2*h+1]));
            mx = fmaxf(mx, __shfl_xor_sync(0xFFFFFFFFu, mx, 1));
            mx = fmaxf(mx, __shfl_xor_sync(0xFFFFFFFFu, mx, 2));
            if (mx > mrow[h]) {        // rare after the first few tiles
                float alpha = fexp2(mrow[h] - mx);
                mrow[h] = mx;
                lrow[h] *= alpha;
#pragma unroll
                for (int nt = 0; nt < 8; nt++) { O[nt][2*h] *= alpha; O[nt][2*h+1] *= alpha; }
            }
            const float mn = mrow[h];
            float sum = 0.0f;
#pragma unroll
            for (int nt = 0; nt < 8; nt++) {
                float p0 = fexp2(S[nt][2*h]   - mn);
                float p1 = fexp2(S[nt][2*h+1] - mn);
                S[nt][2*h] = p0; S[nt][2*h+1] = p1;
                sum += p0 + p1;
            }
            lrow[h] += sum;     // per-lane partial; quad-reduced in epilogue
        }

        // ---- O += P @ V (3 split passes) ----
#pragma unroll
        for (int kc = 0; kc < 4; kc++) {
            uint32_t ah[4], al[4];
            split2(S[2*kc][0],   S[2*kc][1],   ah[0], al[0]);
            split2(S[2*kc][2],   S[2*kc][3],   ah[1], al[1]);
            split2(S[2*kc+1][0], S[2*kc+1][1], ah[2], al[2]);
            split2(S[2*kc+1][2], S[2*kc+1][3], ah[3], al[3]);
            uint32_t vh[4][4], vl[4][4];
#pragma unroll
            for (int p = 0; p < 4; p++) {
                int key = kc * 16 + (lane & 7) + ((lane >> 3) & 1) * 8;
                int ch  = 2 * p + ((lane >> 4) & 1);
                uint32_t ad = bV + key * 128 + ((ch ^ (key & 7)) << 4);
                ldsm4t(vh[p], ad);
                ldsm4t(vl[p], ad + 8192);
            }
#pragma unroll
            for (int nt = 0; nt < 8; nt++) {
                int p = nt >> 1, o = (nt & 1) * 2;
                mma16816(O[nt], ah, vh[p][o], vh[p][o+1]);
                mma16816(O[nt], ah, vl[p][o], vl[p][o+1]);
                mma16816(O[nt], al, vh[p][o], vh[p][o+1]);
            }
        }
        __syncthreads();
    }

    // ---- epilogue: reduce l across quad, write unnormalized partials ----
#pragma unroll
    for (int h = 0; h < 2; h++) {
        float l = lrow[h];
        l += __shfl_xor_sync(0xFFFFFFFFu, l, 1);
        l += __shfl_xor_sync(0xFFFFFFFFu, l, 2);
        const int r = q0 + gid + h * 8;
        if (m4 == 0) { g_m[split][r] = mrow[h]; g_l[split][r] = l; }
#pragma unroll
        for (int nt = 0; nt < 8; nt++) {
            float2 v = make_float2(O[nt][2*h], O[nt][2*h+1]);
            *(float2*)&g_Op[split][r*DOUT + nt*8 + m4*2] = v;
        }
    }
}

// ============================================================
// Combine the 2 split-K partials (m is in log2 domain), float4.
// ============================================================
__global__ __launch_bounds__(256) void combine_kernel(float* __restrict__ out)
{
    int i4 = blockIdx.x * 256 + threadIdx.x;   // float4 index
    int row = i4 >> 4;                          // 16 float4 per row
    float m0 = g_m[0][row], m1 = g_m[1][row];
    float mx = fmaxf(m0, m1);
    float a0 = fexp2(m0 - mx);
    float a1 = fexp2(m1 - mx);
    float inv = 1.0f / (g_l[0][row]*a0 + g_l[1][row]*a1);
    float4 o0 = *(const float4*)&g_Op[0][i4 * 4];
    float4 o1 = *(const float4*)&g_Op[1][i4 * 4];
    float4 r;
    r.x = (o0.x*a0 + o1.x*a1) * inv;
    r.y = (o0.y*a0 + o1.y*a1) * inv;
    r.z = (o0.z*a0 + o1.z*a1) * inv;
    r.w = (o0.w*a0 + o1.w*a1) * inv;
    *(float4*)&out[i4 * 4] = r;
}

// ============================================================
extern "C" void kernel_launch(void* const* d_in, const int* in_sizes, int n_in,
                              void* d_out, int out_size)
{
    (void)in_sizes; (void)n_in; (void)out_size;
    const float* x  = (const float*)d_in[0];
    const float* Wq = (const float*)d_in[1];
    const float* Wk = (const float*)d_in[2];
    const float* Wv = (const float*)d_in[3];
    float* out = (float*)d_out;

    const int attn_smem = 2 * 32768;
    cudaFuncSetAttribute(attn_kernel, cudaFuncAttributeMaxDynamicSharedMemorySize, attn_smem);

    proj_kernel<<<dim3(SEQ/64, 3), 256>>>(x, Wq, Wk, Wv);
    attn_kernel<<<dim3(SEQ/BM, NSPLIT), 256, attn_smem>>>();
    combine_kernel<<<(SEQ*DOUT)/1024, 256>>>(out);
}

// round 10
// speedup vs baseline: 1.0026x; 1.0026x over previous
#include <cuda_runtime.h>
#include <cuda_bf16.h>
#include <cstdint>

#define SEQ  8192
#define DIN  512
#define DOUT 64

#define NSPLIT 2
#define KEYS_PER_SPLIT (SEQ / NSPLIT)
#define BMA  64                         // attn query rows per CTA
#define BN   64
#define NTILES (KEYS_PER_SPLIT / BN)    // 64

// ---------------- device scratch (no allocations allowed) ----------------
__device__ __align__(16) __nv_bfloat16 g_Qhi[SEQ*DOUT];
__device__ __align__(16) __nv_bfloat16 g_Qlo[SEQ*DOUT];
__device__ __align__(16) __nv_bfloat16 g_Khi[SEQ*DOUT];
__device__ __align__(16) __nv_bfloat16 g_Klo[SEQ*DOUT];
__device__ __align__(16) __nv_bfloat16 g_Vhi[SEQ*DOUT];
__device__ __align__(16) __nv_bfloat16 g_Vlo[SEQ*DOUT];
__device__ float g_Op[NSPLIT][SEQ*DOUT];
__device__ float g_m[NSPLIT][SEQ];
__device__ float g_l[NSPLIT][SEQ];

// ---------------- small helpers ----------------
__device__ __forceinline__ uint32_t smem_u32(const void* p) {
    return (uint32_t)__cvta_generic_to_shared((void*)p);
}
__device__ __forceinline__ float fexp2(float x) {
    float y;
    asm("ex2.approx.f32 %0, %1;" : "=f"(y) : "f"(x));
    return y;
}

// split (p0,p1) into packed bf16x2 hi + bf16x2 lo (residual)
__device__ __forceinline__ void split2(float p0, float p1, uint32_t& h, uint32_t& l) {
    uint32_t hh;
    asm("cvt.rn.bf16x2.f32 %0, %1, %2;" : "=r"(hh) : "f"(p1), "f"(p0));
    float f0 = __uint_as_float(hh << 16);
    float f1 = __uint_as_float(hh & 0xFFFF0000u);
    uint32_t ll;
    float r0 = p0 - f0, r1 = p1 - f1;
    asm("cvt.rn.bf16x2.f32 %0, %1, %2;" : "=r"(ll) : "f"(r1), "f"(r0));
    h = hh; l = ll;
}

__device__ __forceinline__ void mma16816(float c[4], const uint32_t a[4],
                                         uint32_t b0, uint32_t b1) {
    asm volatile("mma.sync.aligned.m16n8k16.row.col.f32.bf16.bf16.f32 "
        "{%0,%1,%2,%3}, {%4,%5,%6,%7}, {%8,%9}, {%0,%1,%2,%3};"
        : "+f"(c[0]), "+f"(c[1]), "+f"(c[2]), "+f"(c[3])
        : "r"(a[0]), "r"(a[1]), "r"(a[2]), "r"(a[3]), "r"(b0), "r"(b1));
}
__device__ __forceinline__ void ldsm4(uint32_t r[4], uint32_t addr) {
    asm volatile("ldmatrix.sync.aligned.m8n8.x4.shared.b16 {%0,%1,%2,%3}, [%4];"
        : "=r"(r[0]), "=r"(r[1]), "=r"(r[2]), "=r"(r[3]) : "r"(addr));
}
__device__ __forceinline__ void ldsm4t(uint32_t r[4], uint32_t addr) {
    asm volatile("ldmatrix.sync.aligned.m8n8.x4.trans.shared.b16 {%0,%1,%2,%3}, [%4];"
        : "=r"(r[0]), "=r"(r[1]), "=r"(r[2]), "=r"(r[3]) : "r"(addr));
}

// ============================================================
// Projection via HMMA split-bf16 (3 passes): out = x @ W.
// BM=64 rows/CTA -> grid (128, 3); 2 CTAs/SM; register prefetch
// pipelines kt+1's LDGs under kt's MMA phase. (R7 version, kept.)
// ============================================================
#define PJ_XHI 0
#define PJ_XLO 8192
#define PJ_WHI 16384
#define PJ_WLO 24576

__global__ __launch_bounds__(256, 2) void proj_kernel(
    const float* __restrict__ x,  const float* __restrict__ Wq,
    const float* __restrict__ Wk, const float* __restrict__ Wv)
{
    __shared__ __align__(16) char sm[32768];
    const uint32_t smb = smem_u32(sm);

    const int which = blockIdx.y;
    const float* W = (which == 0) ? Wq : ((which == 1) ? Wk : Wv);
    __nv_bfloat16* hiArr = (which == 0) ? g_Qhi : ((which == 1) ? g_Khi : g_Vhi);
    __nv_bfloat16* loArr = (which == 0) ? g_Qlo : ((which == 1) ? g_Klo : g_Vlo);
    // Q: 1/sqrt(64) * log2(e) so scores land in the log2 domain
    const float scale = (which == 0) ? 0.18033688011112042f : 1.0f;

    const int row0 = blockIdx.x * 64;
    const int tid  = threadIdx.x;
    const int lane = tid & 31;
    const int wid  = tid >> 5;
    const int wm   = (wid & 3) * 16;   // m16 tile
    const int nh   = (wid >> 2) * 32;  // n32 half

    const int i0 = tid, i1 = tid + 256;
    const int r0c = i0 >> 3, c0c = i0 & 7;
    const int r1c = i1 >> 3, c1c = i1 & 7;
    const int xoff0 = r0c * 128 + ((c0c ^ (r0c & 7)) << 4);
    const int xoff1 = r1c * 128 + ((c1c ^ (r1c & 7)) << 4);

    float C[4][4];
#pragma unroll
    for (int nt = 0; nt < 4; nt++)
#pragma unroll
        for (int c = 0; c < 4; c++) C[nt][c] = 0.0f;

    float4 xa[2][2], wa[2][2];
    {
        const float* s0 = x + (row0 + r0c) * DIN + c0c * 8;
        const float* s1 = x + (row0 + r1c) * DIN + c1c * 8;
        xa[0][0] = *(const float4*)s0; xa[0][1] = *(const float4*)(s0 + 4);
        xa[1][0] = *(const float4*)s1; xa[1][1] = *(const float4*)(s1 + 4);
        const float* w0 = W + r0c * DOUT + c0c * 8;
        const float* w1 = W + r1c * DOUT + c1c * 8;
        wa[0][0] = *(const float4*)w0; wa[0][1] = *(const float4*)(w0 + 4);
        wa[1][0] = *(const float4*)w1; wa[1][1] = *(const float4*)(w1 + 4);
    }

    for (int kt = 0; kt < 8; kt++) {
        __syncthreads();
#pragma unroll
        for (int j = 0; j < 2; j++) {
            uint32_t h0,l0,h1,l1,h2,l2,h3,l3;
            split2(xa[j][0].x, xa[j][0].y, h0, l0);
            split2(xa[j][0].z, xa[j][0].w, h1, l1);
            split2(xa[j][1].x, xa[j][1].y, h2, l2);
            split2(xa[j][1].z, xa[j][1].w, h3, l3);
            int off = (j == 0) ? xoff0 : xoff1;
            *(uint4*)(sm + PJ_XHI + off) = make_uint4(h0, h1, h2, h3);
            *(uint4*)(sm + PJ_XLO + off) = make_uint4(l0, l1, l2, l3);
            split2(wa[j][0].x, wa[j][0].y, h0, l0);
            split2(wa[j][0].z, wa[j][0].w, h1, l1);
            split2(wa[j][1].x, wa[j][1].y, h2, l2);
            split2(wa[j][1].z, wa[j][1].w, h3, l3);
            *(uint4*)(sm + PJ_WHI + off) = make_uint4(h0, h1, h2, h3);
            *(uint4*)(sm + PJ_WLO + off) = make_uint4(l0, l1, l2, l3);
        }
        if (kt < 7) {
            const int k1 = (kt + 1) * 64;
            const float* s0 = x + (row0 + r0c) * DIN + k1 + c0c * 8;
            const float* s1 = x + (row0 + r1c) * DIN + k1 + c1c * 8;
            xa[0][0] = *(const float4*)s0; xa[0][1] = *(const float4*)(s0 + 4);
            xa[1][0] = *(const float4*)s1; xa[1][1] = *(const float4*)(s1 + 4);
            const float* w0 = W + (k1 + r0c) * DOUT + c0c * 8;
            const float* w1 = W + (k1 + r1c) * DOUT + c1c * 8;
            wa[0][0] = *(const float4*)w0; wa[0][1] = *(const float4*)(w0 + 4);
            wa[1][0] = *(const float4*)w1; wa[1][1] = *(const float4*)(w1 + 4);
        }
        __syncthreads();

#pragma unroll
        for (int kc = 0; kc < 4; kc++) {
            int arow = wm + (lane & 7) + ((lane >> 3) & 1) * 8;
            int ach  = kc * 2 + (lane >> 4);
            uint32_t ad = smb + PJ_XHI + arow * 128 + ((ach ^ (arow & 7)) << 4);
            uint32_t ah[4], al[4];
            ldsm4(ah, ad);
            ldsm4(al, ad + 8192);
            uint32_t bh[2][4], bl[2][4];
            int krow = kc * 16 + (lane & 7) + ((lane >> 3) & 1) * 8;
#pragma unroll
            for (int p = 0; p < 2; p++) {
                int ch = (nh >> 3) + 2 * p + (lane >> 4);
                uint32_t bd = smb + PJ_WHI + krow * 128 + ((ch ^ (krow & 7)) << 4);
                ldsm4t(bh[p], bd);
                ldsm4t(bl[p], bd + 8192);
            }
#pragma unroll
            for (int nt = 0; nt < 4; nt++) {
                int p = nt >> 1, o = (nt & 1) * 2;
                mma16816(C[nt], ah, bh[p][o], bh[p][o+1]);
                mma16816(C[nt], ah, bl[p][o], bl[p][o+1]);
                mma16816(C[nt], al, bh[p][o], bh[p][o+1]);
            }
        }
    }

    const int gid = lane >> 2, m4 = lane & 3;
#pragma unroll
    for (int nt = 0; nt < 4; nt++) {
        uint32_t h, l;
        const int row = row0 + wm + gid;
        const int col = nh + nt * 8 + m4 * 2;
        split2(C[nt][0] * scale, C[nt][1] * scale, h, l);
        *(uint32_t*)&hiArr[row * DOUT + col] = h;
        *(uint32_t*)&loArr[row * DOUT + col] = l;
        split2(C[nt][2] * scale, C[nt][3] * scale, h, l);
        *(uint32_t*)&hiArr[(row + 8) * DOUT + col] = h;
        *(uint32_t*)&loArr[(row + 8) * DOUT + col] = l;
    }
}

// ============================================================
// HMMA flash attention (split-bf16 3-pass), cp.async double-buffered.
// BMA=64 q-rows per 128-thread CTA (4 warps x 16 rows), 2 CTAs/SM so
// one CTA's softmax phase hides under the other's MMA burst.
// smem stage (32KB): KHI 0, KLO 8192, VHI 16384, VLO 24576; rows 128B,
// 16B-chunk xor-swizzle: chunk c of row r stored at (c ^ (r&7)).
// ============================================================
__device__ __forceinline__ void issue_tile_load(uint32_t smb, int stage, int kb, int tid) {
#pragma unroll
    for (int j = 0; j < 16; j++) {
        int i = tid + 128 * j;          // 0..2047
        int sel = i >> 9;               // 0 khi, 1 klo, 2 vhi, 3 vlo
        int r = (i >> 3) & 63;
        int c = i & 7;
        const __nv_bfloat16* base = (sel == 0) ? g_Khi : (sel == 1) ? g_Klo
                                  : (sel == 2) ? g_Vhi : g_Vlo;
        const __nv_bfloat16* src = base + (kb + r) * DOUT + c * 8;
        uint32_t dst = smb + stage * 32768 + sel * 8192 + r * 128 + ((c ^ (r & 7)) << 4);
        unsigned long long g = (unsigned long long)__cvta_generic_to_global((void*)src);
        asm volatile("cp.async.cg.shared.global [%0], [%1], 16;" :: "r"(dst), "l"(g) : "memory");
    }
}

__global__ __launch_bounds__(128, 2) void attn_kernel()
{
    extern __shared__ char sm[];
    const uint32_t smb = smem_u32(sm);
    const int tid  = threadIdx.x;
    const int lane = tid & 31;
    const int wid  = tid >> 5;      // 0..3
    const int gid  = lane >> 2;     // row group within fragment
    const int m4   = lane & 3;      // col pair within fragment
    const int row0 = blockIdx.x * BMA;
    const int split = blockIdx.y;
    const int kb0  = split * KEYS_PER_SPLIT;
    const int q0   = row0 + wid * 16;

    // ---- persistent Q fragments (hi/lo), straight from gmem ----
    uint32_t qhi[4][4], qlo[4][4];
#pragma unroll
    for (int kc = 0; kc < 4; kc++) {
        const int base = (q0 + gid) * DOUT + kc * 16 + m4 * 2;
        qhi[kc][0] = *(const uint32_t*)&g_Qhi[base];
        qhi[kc][1] = *(const uint32_t*)&g_Qhi[base + 8*DOUT];
        qhi[kc][2] = *(const uint32_t*)&g_Qhi[base + 8];
        qhi[kc][3] = *(const uint32_t*)&g_Qhi[base + 8*DOUT + 8];
        qlo[kc][0] = *(const uint32_t*)&g_Qlo[base];
        qlo[kc][1] = *(const uint32_t*)&g_Qlo[base + 8*DOUT];
        qlo[kc][2] = *(const uint32_t*)&g_Qlo[base + 8];
        qlo[kc][3] = *(const uint32_t*)&g_Qlo[base + 8*DOUT + 8];
    }

    float O[8][4];
#pragma unroll
    for (int nt = 0; nt < 8; nt++)
#pragma unroll
        for (int c = 0; c < 4; c++) O[nt][c] = 0.0f;
    float mrow[2] = {-1e30f, -1e30f};
    float lrow[2] = {0.0f, 0.0f};

    issue_tile_load(smb, 0, kb0, tid);
    asm volatile("cp.async.commit_group;" ::: "memory");

    for (int t = 0; t < NTILES; t++) {
        if (t + 1 < NTILES) {
            issue_tile_load(smb, (t + 1) & 1, kb0 + (t + 1) * BN, tid);
            asm volatile("cp.async.commit_group;" ::: "memory");
            asm volatile("cp.async.wait_group 1;" ::: "memory");
        } else {
            asm volatile("cp.async.wait_group 0;" ::: "memory");
        }
        __syncthreads();

        const uint32_t bK = smb + (t & 1) * 32768;
        const uint32_t bV = bK + 16384;

        // ---- S = Q @ K^T (3 split passes), fp32 accum, log2 domain ----
        float S[8][4];
#pragma unroll
        for (int nt = 0; nt < 8; nt++)
#pragma unroll
            for (int c = 0; c < 4; c++) S[nt][c] = 0.0f;

#pragma unroll
        for (int kc = 0; kc < 4; kc++) {
            uint32_t bh[4][4], bl[4][4];
#pragma unroll
            for (int p = 0; p < 4; p++) {
                int key = p * 16 + (lane & 7) + ((lane >> 4) & 1) * 8;
                int ch  = kc * 2 + ((lane >> 3) & 1);
                uint32_t ad = bK + key * 128 + ((ch ^ (key & 7)) << 4);
                ldsm4(bh[p], ad);
                ldsm4(bl[p], ad + 8192);
            }
#pragma unroll
            for (int nt = 0; nt < 8; nt++) {
                int p = nt >> 1, o = (nt & 1) * 2;
                mma16816(S[nt], qhi[kc], bh[p][o], bh[p][o+1]);
                mma16816(S[nt], qhi[kc], bl[p][o], bl[p][o+1]);
                mma16816(S[nt], qlo[kc], bh[p][o], bh[p][o+1]);
            }
        }

        // ---- online softmax, base 2 (rows fully warp-local) ----
#pragma unroll
        for (int h = 0; h < 2; h++) {
            float mx = -1e30f;
#pragma unroll
            for (int nt = 0; nt < 8; nt++)
                mx = fmaxf(mx, fmaxf(S[nt][2*h], S[nt][2*h+1]));
            mx = fmaxf(mx, __shfl_xor_sync(0xFFFFFFFFu, mx, 1));
            mx = fmaxf(mx, __shfl_xor_sync(0xFFFFFFFFu, mx, 2));
            if (mx > mrow[h]) {        // rare after the first few tiles
                float alpha = fexp2(mrow[h] - mx);
                mrow[h] = mx;
                lrow[h] *= alpha;
#pragma unroll
                for (int nt = 0; nt < 8; nt++) { O[nt][2*h] *= alpha; O[nt][2*h+1] *= alpha; }
            }
            const float mn = mrow[h];
            float sum = 0.0f;
#pragma unroll
            for (int nt = 0; nt < 8; nt++) {
                float p0 = fexp2(S[nt][2*h]   - mn);
                float p1 = fexp2(S[nt][2*h+1] - mn);
                S[nt][2*h] = p0; S[nt][2*h+1] = p1;
                sum += p0 + p1;
            }
            lrow[h] += sum;     // per-lane partial; quad-reduced in epilogue
        }

        // ---- O += P @ V (3 split passes) ----
#pragma unroll
        for (int kc = 0; kc < 4; kc++) {
            uint32_t ah[4], al[4];
            split2(S[2*kc][0],   S[2*kc][1],   ah[0], al[0]);
            split2(S[2*kc][2],   S[2*kc][3],   ah[1], al[1]);
            split2(S[2*kc+1][0], S[2*kc+1][1], ah[2], al[2]);
            split2(S[2*kc+1][2], S[2*kc+1][3], ah[3], al[3]);
            uint32_t vh[4][4], vl[4][4];
#pragma unroll
            for (int p = 0; p < 4; p++) {
                int key = kc * 16 + (lane & 7) + ((lane >> 3) & 1) * 8;
                int ch  = 2 * p + ((lane >> 4) & 1);
                uint32_t ad = bV + key * 128 + ((ch ^ (key & 7)) << 4);
                ldsm4t(vh[p], ad);
                ldsm4t(vl[p], ad + 8192);
            }
#pragma unroll
            for (int nt = 0; nt < 8; nt++) {
                int p = nt >> 1, o = (nt & 1) * 2;
                mma16816(O[nt], ah, vh[p][o], vh[p][o+1]);
                mma16816(O[nt], ah, vl[p][o], vl[p][o+1]);
                mma16816(O[nt], al, vh[p][o], vh[p][o+1]);
            }
        }
        __syncthreads();
    }

    // ---- epilogue: reduce l across quad, write unnormalized partials ----
#pragma unroll
    for (int h = 0; h < 2; h++) {
        float l = lrow[h];
        l += __shfl_xor_sync(0xFFFFFFFFu, l, 1);
        l += __shfl_xor_sync(0xFFFFFFFFu, l, 2);
        const int r = q0 + gid + h * 8;
        if (m4 == 0) { g_m[split][r] = mrow[h]; g_l[split][r] = l; }
#pragma unroll
        for (int nt = 0; nt < 8; nt++) {
            float2 v = make_float2(O[nt][2*h], O[nt][2*h+1]);
            *(float2*)&g_Op[split][r*DOUT + nt*8 + m4*2] = v;
        }
    }
}

// ============================================================
// Combine the 2 split-K partials (m is in log2 domain), float4.
// ============================================================
__global__ __launch_bounds__(256) void combine_kernel(float* __restrict__ out)
{
    int i4 = blockIdx.x * 256 + threadIdx.x;   // float4 index
    int row = i4 >> 4;                          // 16 float4 per row
    float m0 = g_m[0][row], m1 = g_m[1][row];
    float mx = fmaxf(m0, m1);
    float a0 = fexp2(m0 - mx);
    float a1 = fexp2(m1 - mx);
    float inv = 1.0f / (g_l[0][row]*a0 + g_l[1][row]*a1);
    float4 o0 = *(const float4*)&g_Op[0][i4 * 4];
    float4 o1 = *(const float4*)&g_Op[1][i4 * 4];
    float4 r;
    r.x = (o0.x*a0 + o1.x*a1) * inv;
    r.y = (o0.y*a0 + o1.y*a1) * inv;
    r.z = (o0.z*a0 + o1.z*a1) * inv;
    r.w = (o0.w*a0 + o1.w*a1) * inv;
    *(float4*)&out[i4 * 4] = r;
}

// ============================================================
extern "C" void kernel_launch(void* const* d_in, const int* in_sizes, int n_in,
                              void* d_out, int out_size)
{
    (void)in_sizes; (void)n_in; (void)out_size;
    const float* x  = (const float*)d_in[0];
    const float* Wq = (const float*)d_in[1];
    const float* Wk = (const float*)d_in[2];
    const float* Wv = (const float*)d_in[3];
    float* out = (float*)d_out;

    const int attn_smem = 2 * 32768;
    cudaFuncSetAttribute(attn_kernel, cudaFuncAttributeMaxDynamicSharedMemorySize, attn_smem);

    proj_kernel<<<dim3(SEQ/64, 3), 256>>>(x, Wq, Wk, Wv);
    attn_kernel<<<dim3(SEQ/BMA, NSPLIT), 128, attn_smem>>>();
    combine_kernel<<<(SEQ*DOUT)/1024, 256>>>(out);
}

// round 11
// speedup vs baseline: 1.2814x; 1.2782x over previous
#include <cuda_runtime.h>
#include <cuda_bf16.h>
#include <cuda_fp16.h>
#include <cstdint>

#define SEQ  8192
#define DIN  512
#define DOUT 64

#define NSPLIT 2
#define KEYS_PER_SPLIT (SEQ / NSPLIT)
#define BM   128                        // attn query rows per CTA
#define BN   64
#define NTILES (KEYS_PER_SPLIT / BN)    // 64
#define STAGE_BYTES 24576               // KHI 8K + KLO 8K + VH 8K

// ---------------- device scratch (no allocations allowed) ----------------
__device__ __align__(16) __nv_bfloat16 g_Qhi[SEQ*DOUT];
__device__ __align__(16) __nv_bfloat16 g_Qlo[SEQ*DOUT];
__device__ __align__(16) __nv_bfloat16 g_Khi[SEQ*DOUT];
__device__ __align__(16) __nv_bfloat16 g_Klo[SEQ*DOUT];
__device__ __align__(16) __half        g_Vh [SEQ*DOUT];
__device__ float g_Op[NSPLIT][SEQ*DOUT];
__device__ float g_m[NSPLIT][SEQ];
__device__ float g_l[NSPLIT][SEQ];

// ---------------- small helpers ----------------
__device__ __forceinline__ uint32_t smem_u32(const void* p) {
    return (uint32_t)__cvta_generic_to_shared((void*)p);
}
__device__ __forceinline__ float fexp2(float x) {
    float y;
    asm("ex2.approx.f32 %0, %1;" : "=f"(y) : "f"(x));
    return y;
}
// pack (lo, hi) floats into one fp16x2 register
__device__ __forceinline__ uint32_t packf16(float lo, float hi) {
    uint32_t d;
    asm("cvt.rn.f16x2.f32 %0, %1, %2;" : "=r"(d) : "f"(hi), "f"(lo));
    return d;
}

// split (p0,p1) into packed bf16x2 hi + bf16x2 lo (residual)
__device__ __forceinline__ void split2(float p0, float p1, uint32_t& h, uint32_t& l) {
    uint32_t hh;
    asm("cvt.rn.bf16x2.f32 %0, %1, %2;" : "=r"(hh) : "f"(p1), "f"(p0));
    float f0 = __uint_as_float(hh << 16);
    float f1 = __uint_as_float(hh & 0xFFFF0000u);
    uint32_t ll;
    float r0 = p0 - f0, r1 = p1 - f1;
    asm("cvt.rn.bf16x2.f32 %0, %1, %2;" : "=r"(ll) : "f"(r1), "f"(r0));
    h = hh; l = ll;
}

__device__ __forceinline__ void mma16816(float c[4], const uint32_t a[4],
                                         uint32_t b0, uint32_t b1) {
    asm volatile("mma.sync.aligned.m16n8k16.row.col.f32.bf16.bf16.f32 "
        "{%0,%1,%2,%3}, {%4,%5,%6,%7}, {%8,%9}, {%0,%1,%2,%3};"
        : "+f"(c[0]), "+f"(c[1]), "+f"(c[2]), "+f"(c[3])
        : "r"(a[0]), "r"(a[1]), "r"(a[2]), "r"(a[3]), "r"(b0), "r"(b1));
}
__device__ __forceinline__ void mma16816f16(float c[4], const uint32_t a[4],
                                            uint32_t b0, uint32_t b1) {
    asm volatile("mma.sync.aligned.m16n8k16.row.col.f32.f16.f16.f32 "
        "{%0,%1,%2,%3}, {%4,%5,%6,%7}, {%8,%9}, {%0,%1,%2,%3};"
        : "+f"(c[0]), "+f"(c[1]), "+f"(c[2]), "+f"(c[3])
        : "r"(a[0]), "r"(a[1]), "r"(a[2]), "r"(a[3]), "r"(b0), "r"(b1));
}
__device__ __forceinline__ void ldsm4(uint32_t r[4], uint32_t addr) {
    asm volatile("ldmatrix.sync.aligned.m8n8.x4.shared.b16 {%0,%1,%2,%3}, [%4];"
        : "=r"(r[0]), "=r"(r[1]), "=r"(r[2]), "=r"(r[3]) : "r"(addr));
}
__device__ __forceinline__ void ldsm4t(uint32_t r[4], uint32_t addr) {
    asm volatile("ldmatrix.sync.aligned.m8n8.x4.trans.shared.b16 {%0,%1,%2,%3}, [%4];"
        : "=r"(r[0]), "=r"(r[1]), "=r"(r[2]), "=r"(r[3]) : "r"(addr));
}

// ============================================================
// Projection via HMMA split-bf16 (3 passes): out = x @ W.
// BM=64 rows/CTA -> grid (128, 3); 2 CTAs/SM; register prefetch.
// Q/K epilogues write split bf16 hi/lo; V epilogue writes fp16.
// ============================================================
#define PJ_XHI 0
#define PJ_XLO 8192
#define PJ_WHI 16384
#define PJ_WLO 24576

__global__ __launch_bounds__(256, 2) void proj_kernel(
    const float* __restrict__ x,  const float* __restrict__ Wq,
    const float* __restrict__ Wk, const float* __restrict__ Wv)
{
    __shared__ __align__(16) char sm[32768];
    const uint32_t smb = smem_u32(sm);

    const int which = blockIdx.y;
    const float* W = (which == 0) ? Wq : ((which == 1) ? Wk : Wv);
    __nv_bfloat16* hiArr = (which == 0) ? g_Qhi : g_Khi;   // unused for V
    __nv_bfloat16* loArr = (which == 0) ? g_Qlo : g_Klo;
    // Q: 1/sqrt(64) * log2(e) so scores land in the log2 domain
    const float scale = (which == 0) ? 0.18033688011112042f : 1.0f;

    const int row0 = blockIdx.x * 64;
    const int tid  = threadIdx.x;
    const int lane = tid & 31;
    const int wid  = tid >> 5;
    const int wm   = (wid & 3) * 16;   // m16 tile
    const int nh   = (wid >> 2) * 32;  // n32 half

    const int i0 = tid, i1 = tid + 256;
    const int r0c = i0 >> 3, c0c = i0 & 7;
    const int r1c = i1 >> 3, c1c = i1 & 7;
    const int xoff0 = r0c * 128 + ((c0c ^ (r0c & 7)) << 4);
    const int xoff1 = r1c * 128 + ((c1c ^ (r1c & 7)) << 4);

    float C[4][4];
#pragma unroll
    for (int nt = 0; nt < 4; nt++)
#pragma unroll
        for (int c = 0; c < 4; c++) C[nt][c] = 0.0f;

    float4 xa[2][2], wa[2][2];
    {
        const float* s0 = x + (row0 + r0c) * DIN + c0c * 8;
        const float* s1 = x + (row0 + r1c) * DIN + c1c * 8;
        xa[0][0] = *(const float4*)s0; xa[0][1] = *(const float4*)(s0 + 4);
        xa[1][0] = *(const float4*)s1; xa[1][1] = *(const float4*)(s1 + 4);
        const float* w0 = W + r0c * DOUT + c0c * 8;
        const float* w1 = W + r1c * DOUT + c1c * 8;
        wa[0][0] = *(const float4*)w0; wa[0][1] = *(const float4*)(w0 + 4);
        wa[1][0] = *(const float4*)w1; wa[1][1] = *(const float4*)(w1 + 4);
    }

    for (int kt = 0; kt < 8; kt++) {
        __syncthreads();
#pragma unroll
        for (int j = 0; j < 2; j++) {
            uint32_t h0,l0,h1,l1,h2,l2,h3,l3;
            split2(xa[j][0].x, xa[j][0].y, h0, l0);
            split2(xa[j][0].z, xa[j][0].w, h1, l1);
            split2(xa[j][1].x, xa[j][1].y, h2, l2);
            split2(xa[j][1].z, xa[j][1].w, h3, l3);
            int off = (j == 0) ? xoff0 : xoff1;
            *(uint4*)(sm + PJ_XHI + off) = make_uint4(h0, h1, h2, h3);
            *(uint4*)(sm + PJ_XLO + off) = make_uint4(l0, l1, l2, l3);
            split2(wa[j][0].x, wa[j][0].y, h0, l0);
            split2(wa[j][0].z, wa[j][0].w, h1, l1);
            split2(wa[j][1].x, wa[j][1].y, h2, l2);
            split2(wa[j][1].z, wa[j][1].w, h3, l3);
            *(uint4*)(sm + PJ_WHI + off) = make_uint4(h0, h1, h2, h3);
            *(uint4*)(sm + PJ_WLO + off) = make_uint4(l0, l1, l2, l3);
        }
        if (kt < 7) {
            const int k1 = (kt + 1) * 64;
            const float* s0 = x + (row0 + r0c) * DIN + k1 + c0c * 8;
            const float* s1 = x + (row0 + r1c) * DIN + k1 + c1c * 8;
            xa[0][0] = *(const float4*)s0; xa[0][1] = *(const float4*)(s0 + 4);
            xa[1][0] = *(const float4*)s1; xa[1][1] = *(const float4*)(s1 + 4);
            const float* w0 = W + (k1 + r0c) * DOUT + c0c * 8;
            const float* w1 = W + (k1 + r1c) * DOUT + c1c * 8;
            wa[0][0] = *(const float4*)w0; wa[0][1] = *(const float4*)(w0 + 4);
            wa[1][0] = *(const float4*)w1; wa[1][1] = *(const float4*)(w1 + 4);
        }
        __syncthreads();

#pragma unroll
        for (int kc = 0; kc < 4; kc++) {
            int arow = wm + (lane & 7) + ((lane >> 3) & 1) * 8;
            int ach  = kc * 2 + (lane >> 4);
            uint32_t ad = smb + PJ_XHI + arow * 128 + ((ach ^ (arow & 7)) << 4);
            uint32_t ah[4], al[4];
            ldsm4(ah, ad);
            ldsm4(al, ad + 8192);
            uint32_t bh[2][4], bl[2][4];
            int krow = kc * 16 + (lane & 7) + ((lane >> 3) & 1) * 8;
#pragma unroll
            for (int p = 0; p < 2; p++) {
                int ch = (nh >> 3) + 2 * p + (lane >> 4);
                uint32_t bd = smb + PJ_WHI + krow * 128 + ((ch ^ (krow & 7)) << 4);
                ldsm4t(bh[p], bd);
                ldsm4t(bl[p], bd + 8192);
            }
#pragma unroll
            for (int nt = 0; nt < 4; nt++) {
                int p = nt >> 1, o = (nt & 1) * 2;
                mma16816(C[nt], ah, bh[p][o], bh[p][o+1]);
            }
#pragma unroll
            for (int nt = 0; nt < 4; nt++) {
                int p = nt >> 1, o = (nt & 1) * 2;
                mma16816(C[nt], ah, bl[p][o], bl[p][o+1]);
            }
#pragma unroll
            for (int nt = 0; nt < 4; nt++) {
                int p = nt >> 1, o = (nt & 1) * 2;
                mma16816(C[nt], al, bh[p][o], bh[p][o+1]);
            }
        }
    }

    const int gid = lane >> 2, m4 = lane & 3;
    if (which == 2) {
        // V -> single fp16 array
#pragma unroll
        for (int nt = 0; nt < 4; nt++) {
            const int row = row0 + wm + gid;
            const int col = nh + nt * 8 + m4 * 2;
            *(uint32_t*)&g_Vh[row * DOUT + col]       = packf16(C[nt][0], C[nt][1]);
            *(uint32_t*)&g_Vh[(row + 8) * DOUT + col] = packf16(C[nt][2], C[nt][3]);
        }
    } else {
#pragma unroll
        for (int nt = 0; nt < 4; nt++) {
            uint32_t h, l;
            const int row = row0 + wm + gid;
            const int col = nh + nt * 8 + m4 * 2;
            split2(C[nt][0] * scale, C[nt][1] * scale, h, l);
            *(uint32_t*)&hiArr[row * DOUT + col] = h;
            *(uint32_t*)&loArr[row * DOUT + col] = l;
            split2(C[nt][2] * scale, C[nt][3] * scale, h, l);
            *(uint32_t*)&hiArr[(row + 8) * DOUT + col] = h;
            *(uint32_t*)&loArr[(row + 8) * DOUT + col] = l;
        }
    }
}

// ============================================================
// HMMA flash attention: QK split-bf16 3-pass (pass-major order),
// PV single-pass fp16. cp.async double-buffered.
// smem stage (24KB): KHI 0, KLO 8192, VH 16384; rows 128B,
// 16B-chunk xor-swizzle: chunk c of row r stored at (c ^ (r&7)).
// ============================================================
__device__ __forceinline__ void issue_tile_load(uint32_t smb, int stage, int kb, int tid) {
#pragma unroll
    for (int j = 0; j < 6; j++) {
        int i = tid + 256 * j;          // 0..1535
        int sel = i >> 9;               // 0 khi, 1 klo, 2 vh
        int r = (i >> 3) & 63;
        int c = i & 7;
        const char* base = (sel == 0) ? (const char*)g_Khi
                         : (sel == 1) ? (const char*)g_Klo
                                      : (const char*)g_Vh;
        const char* src = base + ((size_t)(kb + r) * DOUT + c * 8) * 2;
        uint32_t dst = smb + stage * STAGE_BYTES + sel * 8192 + r * 128 + ((c ^ (r & 7)) << 4);
        unsigned long long g = (unsigned long long)__cvta_generic_to_global((void*)src);
        asm volatile("cp.async.cg.shared.global [%0], [%1], 16;" :: "r"(dst), "l"(g) : "memory");
    }
}

__global__ __launch_bounds__(256, 1) void attn_kernel()
{
    extern __shared__ char sm[];
    const uint32_t smb = smem_u32(sm);
    const int tid  = threadIdx.x;
    const int lane = tid & 31;
    const int wid  = tid >> 5;      // 0..7
    const int gid  = lane >> 2;     // row group within fragment
    const int m4   = lane & 3;      // col pair within fragment
    const int row0 = blockIdx.x * BM;
    const int split = blockIdx.y;
    const int kb0  = split * KEYS_PER_SPLIT;
    const int q0   = row0 + wid * 16;

    // ---- persistent Q fragments (hi/lo), straight from gmem ----
    uint32_t qhi[4][4], qlo[4][4];
#pragma unroll
    for (int kc = 0; kc < 4; kc++) {
        const int base = (q0 + gid) * DOUT + kc * 16 + m4 * 2;
        qhi[kc][0] = *(const uint32_t*)&g_Qhi[base];
        qhi[kc][1] = *(const uint32_t*)&g_Qhi[base + 8*DOUT];
        qhi[kc][2] = *(const uint32_t*)&g_Qhi[base + 8];
        qhi[kc][3] = *(const uint32_t*)&g_Qhi[base + 8*DOUT + 8];
        qlo[kc][0] = *(const uint32_t*)&g_Qlo[base];
        qlo[kc][1] = *(const uint32_t*)&g_Qlo[base + 8*DOUT];
        qlo[kc][2] = *(const uint32_t*)&g_Qlo[base + 8];
        qlo[kc][3] = *(const uint32_t*)&g_Qlo[base + 8*DOUT + 8];
    }

    float O[8][4];
#pragma unroll
    for (int nt = 0; nt < 8; nt++)
#pragma unroll
        for (int c = 0; c < 4; c++) O[nt][c] = 0.0f;
    float mrow[2] = {-1e30f, -1e30f};
    float lrow[2] = {0.0f, 0.0f};

    issue_tile_load(smb, 0, kb0, tid);
    asm volatile("cp.async.commit_group;" ::: "memory");

    for (int t = 0; t < NTILES; t++) {
        if (t + 1 < NTILES) {
            issue_tile_load(smb, (t + 1) & 1, kb0 + (t + 1) * BN, tid);
            asm volatile("cp.async.commit_group;" ::: "memory");
            asm volatile("cp.async.wait_group 1;" ::: "memory");
        } else {
            asm volatile("cp.async.wait_group 0;" ::: "memory");
        }
        __syncthreads();

        const uint32_t bK = smb + (t & 1) * STAGE_BYTES;
        const uint32_t bV = bK + 16384;

        // ---- S = Q @ K^T (3 split passes, pass-major), log2 domain ----
        float S[8][4];
#pragma unroll
        for (int nt = 0; nt < 8; nt++)
#pragma unroll
            for (int c = 0; c < 4; c++) S[nt][c] = 0.0f;

#pragma unroll
        for (int kc = 0; kc < 4; kc++) {
            uint32_t bh[4][4], bl[4][4];
#pragma unroll
            for (int p = 0; p < 4; p++) {
                int key = p * 16 + (lane & 7) + ((lane >> 4) & 1) * 8;
                int ch  = kc * 2 + ((lane >> 3) & 1);
                uint32_t ad = bK + key * 128 + ((ch ^ (key & 7)) << 4);
                ldsm4(bh[p], ad);
                ldsm4(bl[p], ad + 8192);
            }
            // pass-major: 8 independent accumulator chains between RAW deps
#pragma unroll
            for (int nt = 0; nt < 8; nt++) {
                int p = nt >> 1, o = (nt & 1) * 2;
                mma16816(S[nt], qhi[kc], bh[p][o], bh[p][o+1]);
            }
#pragma unroll
            for (int nt = 0; nt < 8; nt++) {
                int p = nt >> 1, o = (nt & 1) * 2;
                mma16816(S[nt], qhi[kc], bl[p][o], bl[p][o+1]);
            }
#pragma unroll
            for (int nt = 0; nt < 8; nt++) {
                int p = nt >> 1, o = (nt & 1) * 2;
                mma16816(S[nt], qlo[kc], bh[p][o], bh[p][o+1]);
            }
        }

        // ---- online softmax, base 2 (rows fully warp-local) ----
#pragma unroll
        for (int h = 0; h < 2; h++) {
            float mx = -1e30f;
#pragma unroll
            for (int nt = 0; nt < 8; nt++)
                mx = fmaxf(mx, fmaxf(S[nt][2*h], S[nt][2*h+1]));
            mx = fmaxf(mx, __shfl_xor_sync(0xFFFFFFFFu, mx, 1));
            mx = fmaxf(mx, __shfl_xor_sync(0xFFFFFFFFu, mx, 2));
            if (mx > mrow[h]) {        // rare after the first few tiles
                float alpha = fexp2(mrow[h] - mx);
                mrow[h] = mx;
                lrow[h] *= alpha;
#pragma unroll
                for (int nt = 0; nt < 8; nt++) { O[nt][2*h] *= alpha; O[nt][2*h+1] *= alpha; }
            }
            const float mn = mrow[h];
            float sum = 0.0f;
#pragma unroll
            for (int nt = 0; nt < 8; nt++) {
                float p0 = fexp2(S[nt][2*h]   - mn);
                float p1 = fexp2(S[nt][2*h+1] - mn);
                S[nt][2*h] = p0; S[nt][2*h+1] = p1;
                sum += p0 + p1;
            }
            lrow[h] += sum;     // per-lane partial; quad-reduced in epilogue
        }

        // ---- O += P @ V (single fp16 pass) ----
#pragma unroll
        for (int kc = 0; kc < 4; kc++) {
            uint32_t ah[4];
            ah[0] = packf16(S[2*kc][0],   S[2*kc][1]);
            ah[1] = packf16(S[2*kc][2],   S[2*kc][3]);
            ah[2] = packf16(S[2*kc+1][0], S[2*kc+1][1]);
            ah[3] = packf16(S[2*kc+1][2], S[2*kc+1][3]);
            uint32_t vh[4][4];
#pragma unroll
            for (int p = 0; p < 4; p++) {
                int key = kc * 16 + (lane & 7) + ((lane >> 3) & 1) * 8;
                int ch  = 2 * p + ((lane >> 4) & 1);
                uint32_t ad = bV + key * 128 + ((ch ^ (key & 7)) << 4);
                ldsm4t(vh[p], ad);
            }
#pragma unroll
            for (int nt = 0; nt < 8; nt++) {
                int p = nt >> 1, o = (nt & 1) * 2;
                mma16816f16(O[nt], ah, vh[p][o], vh[p][o+1]);
            }
        }
        __syncthreads();
    }

    // ---- epilogue: reduce l across quad, write unnormalized partials ----
#pragma unroll
    for (int h = 0; h < 2; h++) {
        float l = lrow[h];
        l += __shfl_xor_sync(0xFFFFFFFFu, l, 1);
        l += __shfl_xor_sync(0xFFFFFFFFu, l, 2);
        const int r = q0 + gid + h * 8;
        if (m4 == 0) { g_m[split][r] = mrow[h]; g_l[split][r] = l; }
#pragma unroll
        for (int nt = 0; nt < 8; nt++) {
            float2 v = make_float2(O[nt][2*h], O[nt][2*h+1]);
            *(float2*)&g_Op[split][r*DOUT + nt*8 + m4*2] = v;
        }
    }
}

// ============================================================
// Combine the 2 split-K partials (m is in log2 domain), float4.
// ============================================================
__global__ __launch_bounds__(256) void combine_kernel(float* __restrict__ out)
{
    int i4 = blockIdx.x * 256 + threadIdx.x;   // float4 index
    int row = i4 >> 4;                          // 16 float4 per row
    float m0 = g_m[0][row], m1 = g_m[1][row];
    float mx = fmaxf(m0, m1);
    float a0 = fexp2(m0 - mx);
    float a1 = fexp2(m1 - mx);
    float inv = 1.0f / (g_l[0][row]*a0 + g_l[1][row]*a1);
    float4 o0 = *(const float4*)&g_Op[0][i4 * 4];
    float4 o1 = *(const float4*)&g_Op[1][i4 * 4];
    float4 r;
    r.x = (o0.x*a0 + o1.x*a1) * inv;
    r.y = (o0.y*a0 + o1.y*a1) * inv;
    r.z = (o0.z*a0 + o1.z*a1) * inv;
    r.w = (o0.w*a0 + o1.w*a1) * inv;
    *(float4*)&out[i4 * 4] = r;
}

// ============================================================
extern "C" void kernel_launch(void* const* d_in, const int* in_sizes, int n_in,
                              void* d_out, int out_size)
{
    (void)in_sizes; (void)n_in; (void)out_size;
    const float* x  = (const float*)d_in[0];
    const float* Wq = (const float*)d_in[1];
    const float* Wk = (const float*)d_in[2];
    const float* Wv = (const float*)d_in[3];
    float* out = (float*)d_out;

    const int attn_smem = 2 * STAGE_BYTES;   // 48 KB
    cudaFuncSetAttribute(attn_kernel, cudaFuncAttributeMaxDynamicSharedMemorySize, attn_smem);

    proj_kernel<<<dim3(SEQ/64, 3), 256>>>(x, Wq, Wk, Wv);
    attn_kernel<<<dim3(SEQ/BM, NSPLIT), 256, attn_smem>>>();
    combine_kernel<<<(SEQ*DOUT)/1024, 256>>>(out);
}